// round 1
// baseline (speedup 1.0000x reference)
#include <cuda_runtime.h>
#include <math.h>

#define N_NODES 50000
#define N_EDGES 1600000
#define D 128
#define NET 8
#define K_HOPS 10

// ---- static scratch (no runtime allocation allowed) ----
__device__ float g_hA[N_NODES * D];
__device__ float g_hB[N_NODES * D];
__device__ float g_coeff[N_EDGES];
__device__ int   g_srcs[N_EDGES];
__device__ int   g_ptr[N_NODES + 1];
__device__ int   g_indeg[N_NODES];
__device__ int   g_outdeg[N_NODES];
__device__ int   g_fill[N_NODES];
__device__ float g_srcnorm[N_NODES];
__device__ float g_dstnorm9[N_NODES];   // 0.9 * in_deg^-0.5
__device__ float g_gate[NET];           // 1 + sigmoid(MLP(embed[t]))

__device__ __forceinline__ float gelu_exact(float x) {
    return 0.5f * x * (1.0f + erff(x * 0.70710678118654752440f));
}

// ---------------- setup kernels ----------------

__global__ void k_zero() {
    int i = blockIdx.x * blockDim.x + threadIdx.x;
    if (i < N_NODES) { g_indeg[i] = 0; g_outdeg[i] = 0; g_fill[i] = 0; }
}

__global__ void k_deg(const int* __restrict__ src, const int* __restrict__ dst) {
    int e = blockIdx.x * blockDim.x + threadIdx.x;
    if (e < N_EDGES) {
        atomicAdd(&g_outdeg[src[e]], 1);
        atomicAdd(&g_indeg[dst[e]], 1);
    }
}

// 8 etypes, one warp each: gate[t] = 1 + sigmoid(gelu(emb@We1+be1)@We2+be2)
__global__ void k_gate(const float* __restrict__ emb, const float* __restrict__ We1,
                       const float* __restrict__ be1, const float* __restrict__ We2,
                       const float* __restrict__ be2) {
    int w = threadIdx.x >> 5, lane = threadIdx.x & 31;
    if (w < NET) {
        float acc = be1[lane];                         // hidden unit = lane (EDGE_HID=32)
        #pragma unroll 8
        for (int i = 0; i < D; i++)
            acc = fmaf(emb[w * D + i], We1[i * 32 + lane], acc);
        float g = gelu_exact(acc);
        float v = g * We2[lane];
        #pragma unroll
        for (int o = 16; o; o >>= 1) v += __shfl_down_sync(0xffffffffu, v, o);
        if (lane == 0)
            g_gate[w] = 1.0f + 1.0f / (1.0f + expf(-(v + be2[0])));
    }
}

__global__ void k_norm() {
    int i = blockIdx.x * blockDim.x + threadIdx.x;
    if (i < N_NODES) {
        g_srcnorm[i]  = rsqrtf(fmaxf((float)g_outdeg[i], 1.0f));
        g_dstnorm9[i] = 0.9f * rsqrtf(fmaxf((float)g_indeg[i], 1.0f));
    }
}

// single-block exclusive prefix sum of in-degrees -> CSR row pointers
__global__ void k_scan() {
    __shared__ int sm[1024];
    int t = threadIdx.x;
    const int CH = (N_NODES + 1023) / 1024;   // 49
    int beg = t * CH, end = min(beg + CH, N_NODES);
    int s = 0;
    for (int i = beg; i < end; i++) s += g_indeg[i];
    sm[t] = s;
    __syncthreads();
    for (int d = 1; d < 1024; d <<= 1) {
        int add = (t >= d) ? sm[t - d] : 0;
        __syncthreads();
        sm[t] += add;
        __syncthreads();
    }
    int off = sm[t] - s;                       // exclusive prefix for this chunk
    for (int i = beg; i < end; i++) { g_ptr[i] = off; off += g_indeg[i]; }
    if (t == 1023) g_ptr[N_NODES] = off;       // == E
}

// bucket edges by dst; fold gate & src_norm into per-edge coeff
__global__ void k_scatter(const int* __restrict__ src, const int* __restrict__ dst,
                          const int* __restrict__ ef) {
    int e = blockIdx.x * blockDim.x + threadIdx.x;
    if (e < N_EDGES) {
        int d = dst[e], s = src[e];
        int pos = g_ptr[d] + atomicAdd(&g_fill[d], 1);
        g_srcs[pos]  = s;
        g_coeff[pos] = g_gate[ef[e]] * g_srcnorm[s];
    }
}

// ---------------- propagation hop: warp per dst node ----------------
__global__ void __launch_bounds__(256) k_hop(const float* __restrict__ h_in,
                                             float* __restrict__ h_out,
                                             const float* __restrict__ feat0) {
    int gw   = (blockIdx.x * blockDim.x + threadIdx.x) >> 5;  // node id
    int lane = threadIdx.x & 31;
    if (gw >= N_NODES) return;
    int beg = g_ptr[gw], end = g_ptr[gw + 1];
    int col = lane * 4;

    float4 a0 = make_float4(0.f, 0.f, 0.f, 0.f), a1 = a0, a2 = a0, a3 = a0;

    for (int e0 = beg; e0 < end; e0 += 32) {
        int m = min(32, end - e0);
        int s = 0; float c = 0.0f;
        if (lane < m) { s = g_srcs[e0 + lane]; c = g_coeff[e0 + lane]; }
        int i = 0;
        // 4-way unrolled: 4 independent LDG.128 in flight per warp
        for (; i + 4 <= m; i += 4) {
            int   s0 = __shfl_sync(0xffffffffu, s, i);
            int   s1 = __shfl_sync(0xffffffffu, s, i + 1);
            int   s2 = __shfl_sync(0xffffffffu, s, i + 2);
            int   s3 = __shfl_sync(0xffffffffu, s, i + 3);
            float c0 = __shfl_sync(0xffffffffu, c, i);
            float c1 = __shfl_sync(0xffffffffu, c, i + 1);
            float c2 = __shfl_sync(0xffffffffu, c, i + 2);
            float c3 = __shfl_sync(0xffffffffu, c, i + 3);
            float4 v0 = *(const float4*)(h_in + s0 * D + col);
            float4 v1 = *(const float4*)(h_in + s1 * D + col);
            float4 v2 = *(const float4*)(h_in + s2 * D + col);
            float4 v3 = *(const float4*)(h_in + s3 * D + col);
            a0.x = fmaf(c0, v0.x, a0.x); a0.y = fmaf(c0, v0.y, a0.y);
            a0.z = fmaf(c0, v0.z, a0.z); a0.w = fmaf(c0, v0.w, a0.w);
            a1.x = fmaf(c1, v1.x, a1.x); a1.y = fmaf(c1, v1.y, a1.y);
            a1.z = fmaf(c1, v1.z, a1.z); a1.w = fmaf(c1, v1.w, a1.w);
            a2.x = fmaf(c2, v2.x, a2.x); a2.y = fmaf(c2, v2.y, a2.y);
            a2.z = fmaf(c2, v2.z, a2.z); a2.w = fmaf(c2, v2.w, a2.w);
            a3.x = fmaf(c3, v3.x, a3.x); a3.y = fmaf(c3, v3.y, a3.y);
            a3.z = fmaf(c3, v3.z, a3.z); a3.w = fmaf(c3, v3.w, a3.w);
        }
        for (; i < m; i++) {
            int   s0 = __shfl_sync(0xffffffffu, s, i);
            float c0 = __shfl_sync(0xffffffffu, c, i);
            float4 v0 = *(const float4*)(h_in + s0 * D + col);
            a0.x = fmaf(c0, v0.x, a0.x); a0.y = fmaf(c0, v0.y, a0.y);
            a0.z = fmaf(c0, v0.z, a0.z); a0.w = fmaf(c0, v0.w, a0.w);
        }
    }
    float dn = g_dstnorm9[gw];
    float4 f = *(const float4*)(feat0 + gw * D + col);
    float4 o;
    o.x = fmaf(a0.x + a1.x + a2.x + a3.x, dn, 0.1f * f.x);
    o.y = fmaf(a0.y + a1.y + a2.y + a3.y, dn, 0.1f * f.y);
    o.z = fmaf(a0.z + a1.z + a2.z + a3.z, dn, 0.1f * f.z);
    o.w = fmaf(a0.w + a1.w + a2.w + a3.w, dn, 0.1f * f.w);
    *(float4*)(h_out + gw * D + col) = o;
}

// ---------------- fused output MLP: gelu(x@W1+b1)@W2+b2 ----------------
#define MLP_ROWS 64
#define WS_STRIDE 132
#define XS_STRIDE 136

__global__ void __launch_bounds__(256) k_mlp(const float* __restrict__ x,
                                             const float* __restrict__ W1,
                                             const float* __restrict__ b1,
                                             const float* __restrict__ W2,
                                             const float* __restrict__ b2,
                                             float* __restrict__ out) {
    extern __shared__ float smem[];
    float* Ws = smem;                           // 128 x 132
    float* xs = smem + 128 * WS_STRIDE;         // 64 x 136
    float* ts = xs + MLP_ROWS * XS_STRIDE;      // 64 x 136
    int tid = threadIdx.x;
    int row0 = blockIdx.x * MLP_ROWS;

    for (int idx = tid; idx < 128 * 128; idx += 256)
        Ws[(idx >> 7) * WS_STRIDE + (idx & 127)] = W1[idx];
    for (int idx = tid; idx < MLP_ROWS * 128; idx += 256) {
        int r = idx >> 7, c = idx & 127, gr = row0 + r;
        xs[r * XS_STRIDE + c] = (gr < N_NODES) ? x[gr * D + c] : 0.0f;
    }
    __syncthreads();

    int rg = tid >> 4, cg = tid & 15;
    int r0 = rg * 4, c0 = cg * 8;
    float acc[4][8];
    #pragma unroll
    for (int i = 0; i < 4; i++)
        #pragma unroll
        for (int j = 0; j < 8; j++) acc[i][j] = 0.0f;

    #pragma unroll 8
    for (int k = 0; k < 128; k++) {
        float4 w0 = *(const float4*)&Ws[k * WS_STRIDE + c0];
        float4 w1 = *(const float4*)&Ws[k * WS_STRIDE + c0 + 4];
        float b[8] = {w0.x, w0.y, w0.z, w0.w, w1.x, w1.y, w1.z, w1.w};
        float a[4];
        #pragma unroll
        for (int i = 0; i < 4; i++) a[i] = xs[(r0 + i) * XS_STRIDE + k];
        #pragma unroll
        for (int i = 0; i < 4; i++)
            #pragma unroll
            for (int j = 0; j < 8; j++) acc[i][j] = fmaf(a[i], b[j], acc[i][j]);
    }
    #pragma unroll
    for (int j = 0; j < 8; j++) {
        float bb = b1[c0 + j];
        #pragma unroll
        for (int i = 0; i < 4; i++)
            ts[(r0 + i) * XS_STRIDE + c0 + j] = gelu_exact(acc[i][j] + bb);
    }
    __syncthreads();
    for (int idx = tid; idx < 128 * 128; idx += 256)
        Ws[(idx >> 7) * WS_STRIDE + (idx & 127)] = W2[idx];
    #pragma unroll
    for (int i = 0; i < 4; i++)
        #pragma unroll
        for (int j = 0; j < 8; j++) acc[i][j] = 0.0f;
    __syncthreads();

    #pragma unroll 8
    for (int k = 0; k < 128; k++) {
        float4 w0 = *(const float4*)&Ws[k * WS_STRIDE + c0];
        float4 w1 = *(const float4*)&Ws[k * WS_STRIDE + c0 + 4];
        float b[8] = {w0.x, w0.y, w0.z, w0.w, w1.x, w1.y, w1.z, w1.w};
        float a[4];
        #pragma unroll
        for (int i = 0; i < 4; i++) a[i] = ts[(r0 + i) * XS_STRIDE + k];
        #pragma unroll
        for (int i = 0; i < 4; i++)
            #pragma unroll
            for (int j = 0; j < 8; j++) acc[i][j] = fmaf(a[i], b[j], acc[i][j]);
    }
    #pragma unroll
    for (int j = 0; j < 8; j++) {
        float bb = b2[c0 + j];
        #pragma unroll
        for (int i = 0; i < 4; i++) {
            int gr = row0 + r0 + i;
            if (gr < N_NODES) out[gr * D + c0 + j] = acc[i][j] + bb;
        }
    }
}

// ---------------- launch ----------------
extern "C" void kernel_launch(void* const* d_in, const int* in_sizes, int n_in,
                              void* d_out, int out_size) {
    const float* feat  = (const float*)d_in[0];
    const int*   e_ft  = (const int*)  d_in[1];
    const int*   src   = (const int*)  d_in[2];
    const int*   dst   = (const int*)  d_in[3];
    const float* emb   = (const float*)d_in[4];
    const float* We1   = (const float*)d_in[5];
    const float* be1   = (const float*)d_in[6];
    const float* We2   = (const float*)d_in[7];
    const float* be2   = (const float*)d_in[8];
    const float* W1    = (const float*)d_in[9];
    const float* b1    = (const float*)d_in[10];
    const float* W2    = (const float*)d_in[11];
    const float* b2    = (const float*)d_in[12];
    float* out = (float*)d_out;

    k_zero<<<(N_NODES + 255) / 256, 256>>>();
    k_deg<<<(N_EDGES + 255) / 256, 256>>>(src, dst);
    k_gate<<<1, 256>>>(emb, We1, be1, We2, be2);
    k_norm<<<(N_NODES + 255) / 256, 256>>>();
    k_scan<<<1, 1024>>>();
    k_scatter<<<(N_EDGES + 255) / 256, 256>>>(src, dst, e_ft);

    float *hA = nullptr, *hB = nullptr;
    cudaGetSymbolAddress((void**)&hA, g_hA);
    cudaGetSymbolAddress((void**)&hB, g_hB);

    const float* hin = feat;
    float* hout = hA;
    int hop_blocks = (N_NODES * 32 + 255) / 256;   // warp per node
    for (int k = 0; k < K_HOPS; k++) {
        k_hop<<<hop_blocks, 256>>>(hin, hout, feat);
        hin  = hout;
        hout = (hout == hA) ? hB : hA;
    }

    size_t smem_bytes = (size_t)(128 * WS_STRIDE + 2 * MLP_ROWS * XS_STRIDE) * sizeof(float);
    cudaFuncSetAttribute(k_mlp, cudaFuncAttributeMaxDynamicSharedMemorySize, (int)smem_bytes);
    k_mlp<<<(N_NODES + MLP_ROWS - 1) / MLP_ROWS, 256, smem_bytes>>>(hin, W1, b1, W2, b2, out);
}

// round 2
// speedup vs baseline: 1.2415x; 1.2415x over previous
#include <cuda_runtime.h>
#include <cuda_fp16.h>
#include <math.h>

#define N_NODES 50000
#define N_EDGES 1600000
#define D 128
#define NET 8
#define K_HOPS 10

// ---- static scratch (no runtime allocation allowed) ----
__device__ __half g_h16A[N_NODES * D];
__device__ __half g_h16B[N_NODES * D];
__device__ __half g_f016[N_NODES * D];
__device__ float g_coeff[N_EDGES];
__device__ int   g_srcs[N_EDGES];
__device__ int   g_ptr[N_NODES + 1];
__device__ int   g_indeg[N_NODES];
__device__ int   g_outdeg[N_NODES];
__device__ int   g_fill[N_NODES];
__device__ float g_srcnorm[N_NODES];
__device__ float g_dstnorm9[N_NODES];   // 0.9 * in_deg^-0.5
__device__ float g_gate[NET];           // 1 + sigmoid(MLP(embed[t]))

__device__ __forceinline__ float gelu_exact(float x) {
    return 0.5f * x * (1.0f + erff(x * 0.70710678118654752440f));
}

// ---------------- setup kernels ----------------

__global__ void k_zero() {
    int i = blockIdx.x * blockDim.x + threadIdx.x;
    if (i < N_NODES) { g_indeg[i] = 0; g_outdeg[i] = 0; g_fill[i] = 0; }
}

__global__ void k_deg(const int* __restrict__ src, const int* __restrict__ dst) {
    int e = blockIdx.x * blockDim.x + threadIdx.x;
    if (e < N_EDGES) {
        atomicAdd(&g_outdeg[src[e]], 1);
        atomicAdd(&g_indeg[dst[e]], 1);
    }
}

// convert feat (fp32) -> fp16 copy for residual reads
__global__ void k_cvt(const float* __restrict__ feat) {
    int i = blockIdx.x * blockDim.x + threadIdx.x;   // over N*D/4
    if (i < N_NODES * D / 4) {
        float4 v = *(const float4*)(feat + i * 4);
        __half2 a = __floats2half2_rn(v.x, v.y);
        __half2 b = __floats2half2_rn(v.z, v.w);
        uint2 u;
        u.x = *(unsigned int*)&a;
        u.y = *(unsigned int*)&b;
        *(uint2*)(g_f016 + i * 4) = u;
    }
}

// 8 etypes, one warp each: gate[t] = 1 + sigmoid(gelu(emb@We1+be1)@We2+be2)
__global__ void k_gate(const float* __restrict__ emb, const float* __restrict__ We1,
                       const float* __restrict__ be1, const float* __restrict__ We2,
                       const float* __restrict__ be2) {
    int w = threadIdx.x >> 5, lane = threadIdx.x & 31;
    if (w < NET) {
        float acc = be1[lane];                         // hidden unit = lane (EDGE_HID=32)
        #pragma unroll 8
        for (int i = 0; i < D; i++)
            acc = fmaf(emb[w * D + i], We1[i * 32 + lane], acc);
        float g = gelu_exact(acc);
        float v = g * We2[lane];
        #pragma unroll
        for (int o = 16; o; o >>= 1) v += __shfl_down_sync(0xffffffffu, v, o);
        if (lane == 0)
            g_gate[w] = 1.0f + 1.0f / (1.0f + expf(-(v + be2[0])));
    }
}

__global__ void k_norm() {
    int i = blockIdx.x * blockDim.x + threadIdx.x;
    if (i < N_NODES) {
        g_srcnorm[i]  = rsqrtf(fmaxf((float)g_outdeg[i], 1.0f));
        g_dstnorm9[i] = 0.9f * rsqrtf(fmaxf((float)g_indeg[i], 1.0f));
    }
}

// single-block exclusive prefix sum of in-degrees -> CSR row pointers
__global__ void k_scan() {
    __shared__ int sm[1024];
    int t = threadIdx.x;
    const int CH = (N_NODES + 1023) / 1024;   // 49
    int beg = t * CH, end = min(beg + CH, N_NODES);
    int s = 0;
    for (int i = beg; i < end; i++) s += g_indeg[i];
    sm[t] = s;
    __syncthreads();
    for (int d = 1; d < 1024; d <<= 1) {
        int add = (t >= d) ? sm[t - d] : 0;
        __syncthreads();
        sm[t] += add;
        __syncthreads();
    }
    int off = sm[t] - s;                       // exclusive prefix for this chunk
    for (int i = beg; i < end; i++) { g_ptr[i] = off; off += g_indeg[i]; }
    if (t == 1023) g_ptr[N_NODES] = off;       // == E
}

// bucket edges by dst; fold gate & src_norm into per-edge coeff
__global__ void k_scatter(const int* __restrict__ src, const int* __restrict__ dst,
                          const int* __restrict__ ef) {
    int e = blockIdx.x * blockDim.x + threadIdx.x;
    if (e < N_EDGES) {
        int d = dst[e], s = src[e];
        int pos = g_ptr[d] + atomicAdd(&g_fill[d], 1);
        g_srcs[pos]  = s;
        g_coeff[pos] = g_gate[ef[e]] * g_srcnorm[s];
    }
}

// ---------------- propagation hop: warp per dst node, fp16 storage ----------------
__device__ __forceinline__ void acc4(float4& a, float c, uint2 u) {
    __half2 h01 = *(__half2*)&u.x;
    __half2 h23 = *(__half2*)&u.y;
    float2 f01 = __half22float2(h01);
    float2 f23 = __half22float2(h23);
    a.x = fmaf(c, f01.x, a.x); a.y = fmaf(c, f01.y, a.y);
    a.z = fmaf(c, f23.x, a.z); a.w = fmaf(c, f23.y, a.w);
}

__global__ void __launch_bounds__(256) k_hop(const __half* __restrict__ h_in,
                                             __half* __restrict__ h_out) {
    int gw   = (blockIdx.x * blockDim.x + threadIdx.x) >> 5;  // node id
    int lane = threadIdx.x & 31;
    if (gw >= N_NODES) return;
    int beg = g_ptr[gw], end = g_ptr[gw + 1];
    int col = lane * 4;

    float4 a0 = make_float4(0.f, 0.f, 0.f, 0.f), a1 = a0, a2 = a0, a3 = a0;

    for (int e0 = beg; e0 < end; e0 += 32) {
        int m = min(32, end - e0);
        int s = 0; float c = 0.0f;
        if (lane < m) { s = g_srcs[e0 + lane]; c = g_coeff[e0 + lane]; }
        int i = 0;
        // 4-way unrolled: 4 independent LDG.64 in flight per warp
        for (; i + 4 <= m; i += 4) {
            int   s0 = __shfl_sync(0xffffffffu, s, i);
            int   s1 = __shfl_sync(0xffffffffu, s, i + 1);
            int   s2 = __shfl_sync(0xffffffffu, s, i + 2);
            int   s3 = __shfl_sync(0xffffffffu, s, i + 3);
            float c0 = __shfl_sync(0xffffffffu, c, i);
            float c1 = __shfl_sync(0xffffffffu, c, i + 1);
            float c2 = __shfl_sync(0xffffffffu, c, i + 2);
            float c3 = __shfl_sync(0xffffffffu, c, i + 3);
            uint2 u0 = *(const uint2*)(h_in + s0 * D + col);
            uint2 u1 = *(const uint2*)(h_in + s1 * D + col);
            uint2 u2 = *(const uint2*)(h_in + s2 * D + col);
            uint2 u3 = *(const uint2*)(h_in + s3 * D + col);
            acc4(a0, c0, u0);
            acc4(a1, c1, u1);
            acc4(a2, c2, u2);
            acc4(a3, c3, u3);
        }
        for (; i < m; i++) {
            int   s0 = __shfl_sync(0xffffffffu, s, i);
            float c0 = __shfl_sync(0xffffffffu, c, i);
            uint2 u0 = *(const uint2*)(h_in + s0 * D + col);
            acc4(a0, c0, u0);
        }
    }
    float dn = g_dstnorm9[gw];
    uint2 fu = *(const uint2*)(g_f016 + gw * D + col);
    __half2 fh01 = *(__half2*)&fu.x;
    __half2 fh23 = *(__half2*)&fu.y;
    float2 f01 = __half22float2(fh01);
    float2 f23 = __half22float2(fh23);
    float ox = fmaf(a0.x + a1.x + a2.x + a3.x, dn, 0.1f * f01.x);
    float oy = fmaf(a0.y + a1.y + a2.y + a3.y, dn, 0.1f * f01.y);
    float oz = fmaf(a0.z + a1.z + a2.z + a3.z, dn, 0.1f * f23.x);
    float ow = fmaf(a0.w + a1.w + a2.w + a3.w, dn, 0.1f * f23.y);
    __half2 o01 = __floats2half2_rn(ox, oy);
    __half2 o23 = __floats2half2_rn(oz, ow);
    uint2 ou;
    ou.x = *(unsigned int*)&o01;
    ou.y = *(unsigned int*)&o23;
    *(uint2*)(h_out + gw * D + col) = ou;
}

// ---------------- fused output MLP: gelu(x@W1+b1)@W2+b2 (fp16 input) ----------------
#define MLP_ROWS 64
#define WS_STRIDE 132
#define XS_STRIDE 136

__global__ void __launch_bounds__(256) k_mlp(const __half* __restrict__ x,
                                             const float* __restrict__ W1,
                                             const float* __restrict__ b1,
                                             const float* __restrict__ W2,
                                             const float* __restrict__ b2,
                                             float* __restrict__ out) {
    extern __shared__ float smem[];
    float* Ws = smem;                           // 128 x 132
    float* xs = smem + 128 * WS_STRIDE;         // 64 x 136
    float* ts = xs + MLP_ROWS * XS_STRIDE;      // 64 x 136
    int tid = threadIdx.x;
    int row0 = blockIdx.x * MLP_ROWS;

    for (int idx = tid; idx < 128 * 128; idx += 256)
        Ws[(idx >> 7) * WS_STRIDE + (idx & 127)] = W1[idx];
    for (int idx = tid; idx < MLP_ROWS * 64; idx += 256) {   // half2 granularity
        int r = idx >> 6, c2 = idx & 63, gr = row0 + r;
        float2 v = make_float2(0.f, 0.f);
        if (gr < N_NODES) {
            __half2 h = *(const __half2*)(x + gr * D + c2 * 2);
            v = __half22float2(h);
        }
        xs[r * XS_STRIDE + c2 * 2]     = v.x;
        xs[r * XS_STRIDE + c2 * 2 + 1] = v.y;
    }
    __syncthreads();

    int rg = tid >> 4, cg = tid & 15;
    int r0 = rg * 4, c0 = cg * 8;
    float acc[4][8];
    #pragma unroll
    for (int i = 0; i < 4; i++)
        #pragma unroll
        for (int j = 0; j < 8; j++) acc[i][j] = 0.0f;

    #pragma unroll 8
    for (int k = 0; k < 128; k++) {
        float4 w0 = *(const float4*)&Ws[k * WS_STRIDE + c0];
        float4 w1 = *(const float4*)&Ws[k * WS_STRIDE + c0 + 4];
        float b[8] = {w0.x, w0.y, w0.z, w0.w, w1.x, w1.y, w1.z, w1.w};
        float a[4];
        #pragma unroll
        for (int i = 0; i < 4; i++) a[i] = xs[(r0 + i) * XS_STRIDE + k];
        #pragma unroll
        for (int i = 0; i < 4; i++)
            #pragma unroll
            for (int j = 0; j < 8; j++) acc[i][j] = fmaf(a[i], b[j], acc[i][j]);
    }
    #pragma unroll
    for (int j = 0; j < 8; j++) {
        float bb = b1[c0 + j];
        #pragma unroll
        for (int i = 0; i < 4; i++)
            ts[(r0 + i) * XS_STRIDE + c0 + j] = gelu_exact(acc[i][j] + bb);
    }
    __syncthreads();
    for (int idx = tid; idx < 128 * 128; idx += 256)
        Ws[(idx >> 7) * WS_STRIDE + (idx & 127)] = W2[idx];
    #pragma unroll
    for (int i = 0; i < 4; i++)
        #pragma unroll
        for (int j = 0; j < 8; j++) acc[i][j] = 0.0f;
    __syncthreads();

    #pragma unroll 8
    for (int k = 0; k < 128; k++) {
        float4 w0 = *(const float4*)&Ws[k * WS_STRIDE + c0];
        float4 w1 = *(const float4*)&Ws[k * WS_STRIDE + c0 + 4];
        float b[8] = {w0.x, w0.y, w0.z, w0.w, w1.x, w1.y, w1.z, w1.w};
        float a[4];
        #pragma unroll
        for (int i = 0; i < 4; i++) a[i] = ts[(r0 + i) * XS_STRIDE + k];
        #pragma unroll
        for (int i = 0; i < 4; i++)
            #pragma unroll
            for (int j = 0; j < 8; j++) acc[i][j] = fmaf(a[i], b[j], acc[i][j]);
    }
    #pragma unroll
    for (int j = 0; j < 8; j++) {
        float bb = b2[c0 + j];
        #pragma unroll
        for (int i = 0; i < 4; i++) {
            int gr = row0 + r0 + i;
            if (gr < N_NODES) out[gr * D + c0 + j] = acc[i][j] + bb;
        }
    }
}

// ---------------- launch ----------------
extern "C" void kernel_launch(void* const* d_in, const int* in_sizes, int n_in,
                              void* d_out, int out_size) {
    const float* feat  = (const float*)d_in[0];
    const int*   e_ft  = (const int*)  d_in[1];
    const int*   src   = (const int*)  d_in[2];
    const int*   dst   = (const int*)  d_in[3];
    const float* emb   = (const float*)d_in[4];
    const float* We1   = (const float*)d_in[5];
    const float* be1   = (const float*)d_in[6];
    const float* We2   = (const float*)d_in[7];
    const float* be2   = (const float*)d_in[8];
    const float* W1    = (const float*)d_in[9];
    const float* b1    = (const float*)d_in[10];
    const float* W2    = (const float*)d_in[11];
    const float* b2    = (const float*)d_in[12];
    float* out = (float*)d_out;

    k_zero<<<(N_NODES + 255) / 256, 256>>>();
    k_deg<<<(N_EDGES + 255) / 256, 256>>>(src, dst);
    k_cvt<<<(N_NODES * D / 4 + 255) / 256, 256>>>(feat);
    k_gate<<<1, 256>>>(emb, We1, be1, We2, be2);
    k_norm<<<(N_NODES + 255) / 256, 256>>>();
    k_scan<<<1, 1024>>>();
    k_scatter<<<(N_EDGES + 255) / 256, 256>>>(src, dst, e_ft);

    __half *hA = nullptr, *hB = nullptr, *hF = nullptr;
    cudaGetSymbolAddress((void**)&hA, g_h16A);
    cudaGetSymbolAddress((void**)&hB, g_h16B);
    cudaGetSymbolAddress((void**)&hF, g_f016);

    const __half* hin = hF;        // hop 0 input = fp16 copy of feat
    __half* hout = hA;
    int hop_blocks = (N_NODES * 32 + 255) / 256;   // warp per node
    for (int k = 0; k < K_HOPS; k++) {
        k_hop<<<hop_blocks, 256>>>(hin, hout);
        hin  = hout;
        hout = (hout == hA) ? hB : hA;
    }

    size_t smem_bytes = (size_t)(128 * WS_STRIDE + 2 * MLP_ROWS * XS_STRIDE) * sizeof(float);
    cudaFuncSetAttribute(k_mlp, cudaFuncAttributeMaxDynamicSharedMemorySize, (int)smem_bytes);
    k_mlp<<<(N_NODES + MLP_ROWS - 1) / MLP_ROWS, 256, smem_bytes>>>(hin, W1, b1, W2, b2, out);
}